// round 16
// baseline (speedup 1.0000x reference)
#include <cuda_runtime.h>
#include <cuda_bf16.h>
#include <math.h>

// Problem constants
#define BATCH   2
#define SEQ     2048
#define DIM     512
#define D_INNER 1024
#define D_STATE 16
#define D_CONV  4
#define DT_RANK 32
#define MROWS   (BATCH * SEQ)          // 4096
#define CH      8                      // scan chunks
#define CLEN    (SEQ / CH)             // 256

typedef __nv_bfloat16 bf16;

// ---------------------------------------------------------------------------
// Scratch (static device arrays; no allocation allowed)
// ---------------------------------------------------------------------------
__device__ float g_xz  [MROWS * 2 * D_INNER];
__device__ float g_xc  [MROWS * D_INNER];
__device__ float g_proj[MROWS * 64];
__device__ float g_dt  [MROWS * D_INNER];

__device__ float g_P  [BATCH * 64 * CH * 256];
__device__ float g_q  [BATCH * 64 * CH * 256];
__device__ float g_sin[BATCH * 64 * CH * 256];

__device__ bf16 g_h_hi [MROWS * DIM],      g_h_lo [MROWS * DIM];
__device__ bf16 g_xc_hi[MROWS * D_INNER],  g_xc_lo[MROWS * D_INNER];
__device__ bf16 g_y_hi [MROWS * D_INNER],  g_y_lo [MROWS * D_INNER];
__device__ bf16 g_Win_hi [2 * D_INNER * DIM], g_Win_lo [2 * D_INNER * DIM];
__device__ bf16 g_Wxp_hi [64 * D_INNER],      g_Wxp_lo [64 * D_INNER];
__device__ bf16 g_Wout_hi[DIM * D_INNER],     g_Wout_lo[DIM * D_INNER];

// ---------------------------------------------------------------------------
// Helpers
// ---------------------------------------------------------------------------
__device__ __forceinline__ void split2(float x, bf16& h, bf16& l)
{
    h = __float2bfloat16(x);
    l = __float2bfloat16(x - __bfloat162float(h));
}

__device__ __forceinline__ float softplus_f(float x)
{
    return (x > 20.0f) ? x : log1pf(__expf(x));
}

__device__ __forceinline__ void mma_bf16(float* d,
                                         unsigned a0, unsigned a1,
                                         unsigned a2, unsigned a3,
                                         unsigned b0, unsigned b1)
{
    asm volatile(
        "mma.sync.aligned.m16n8k16.row.col.f32.bf16.bf16.f32 "
        "{%0,%1,%2,%3},{%4,%5,%6,%7},{%8,%9},{%0,%1,%2,%3};"
        : "+f"(d[0]), "+f"(d[1]), "+f"(d[2]), "+f"(d[3])
        : "r"(a0), "r"(a1), "r"(a2), "r"(a3), "r"(b0), "r"(b1));
}

__device__ __forceinline__ void ldsm_x4(unsigned& r0, unsigned& r1,
                                        unsigned& r2, unsigned& r3,
                                        unsigned saddr)
{
    asm volatile("ldmatrix.sync.aligned.m8n8.x4.shared.b16 {%0,%1,%2,%3}, [%4];"
                 : "=r"(r0), "=r"(r1), "=r"(r2), "=r"(r3) : "r"(saddr));
}

__device__ __forceinline__ void cp16(void* smem_dst, const void* gmem_src)
{
    const unsigned sa = (unsigned)__cvta_generic_to_shared(smem_dst);
    asm volatile("cp.async.cg.shared.global [%0], [%1], 16;"
                 :: "r"(sa), "l"(gmem_src));
}
__device__ __forceinline__ void cp_commit()
{
    asm volatile("cp.async.commit_group;");
}
__device__ __forceinline__ void cp_wait0()
{
    asm volatile("cp.async.wait_group 0;");
}

// ---------------------------------------------------------------------------
// Weight splits: two launches (so gemm1 is launch #4 for the profiler)
// ---------------------------------------------------------------------------
#define N4_WIN  (2 * D_INNER * DIM / 4)
#define N4_WXP  (64 * D_INNER / 4)
#define N4_WOUT (DIM * D_INNER / 4)

__global__ void split_win_kernel(const float* __restrict__ W_in,
                                 bf16* __restrict__ hi, bf16* __restrict__ lo)
{
    const int i = blockIdx.x * blockDim.x + threadIdx.x;
    if (i >= N4_WIN) return;
    const float4 v = reinterpret_cast<const float4*>(W_in)[i];
    bf16 h0,h1,h2,h3,l0,l1,l2,l3;
    split2(v.x, h0, l0); split2(v.y, h1, l1);
    split2(v.z, h2, l2); split2(v.w, h3, l3);
    reinterpret_cast<__nv_bfloat162*>(hi)[2*i]   = __halves2bfloat162(h0, h1);
    reinterpret_cast<__nv_bfloat162*>(hi)[2*i+1] = __halves2bfloat162(h2, h3);
    reinterpret_cast<__nv_bfloat162*>(lo)[2*i]   = __halves2bfloat162(l0, l1);
    reinterpret_cast<__nv_bfloat162*>(lo)[2*i+1] = __halves2bfloat162(l2, l3);
}

__global__ void split_rest_kernel(const float* __restrict__ W_xp,
                                  const float* __restrict__ W_out,
                                  bf16* __restrict__ wxh, bf16* __restrict__ wxl,
                                  bf16* __restrict__ woh, bf16* __restrict__ wol)
{
    int i = blockIdx.x * blockDim.x + threadIdx.x;
    const float* src; bf16 *hi, *lo;
    if (i < N4_WXP) {
        src = W_xp; hi = wxh; lo = wxl;
    } else if (i < N4_WXP + N4_WOUT) {
        i -= N4_WXP; src = W_out; hi = woh; lo = wol;
    } else return;

    const float4 v = reinterpret_cast<const float4*>(src)[i];
    bf16 h0,h1,h2,h3,l0,l1,l2,l3;
    split2(v.x, h0, l0); split2(v.y, h1, l1);
    split2(v.z, h2, l2); split2(v.w, h3, l3);
    reinterpret_cast<__nv_bfloat162*>(hi)[2*i]   = __halves2bfloat162(h0, h1);
    reinterpret_cast<__nv_bfloat162*>(hi)[2*i+1] = __halves2bfloat162(h2, h3);
    reinterpret_cast<__nv_bfloat162*>(lo)[2*i]   = __halves2bfloat162(l0, l1);
    reinterpret_cast<__nv_bfloat162*>(lo)[2*i+1] = __halves2bfloat162(l2, l3);
}

// ---------------------------------------------------------------------------
// LayerNorm: one block (128 threads) per row of 512; outputs bf16 hi/lo
// ---------------------------------------------------------------------------
__global__ void ln_kernel(const float* __restrict__ x,
                          const float* __restrict__ g,
                          const float* __restrict__ b,
                          bf16* __restrict__ h_hi, bf16* __restrict__ h_lo)
{
    const int row = blockIdx.x;
    const int tid = threadIdx.x;
    const float4 v = reinterpret_cast<const float4*>(x + (size_t)row * DIM)[tid];

    float s  = v.x + v.y + v.z + v.w;
    float sq = v.x*v.x + v.y*v.y + v.z*v.z + v.w*v.w;

    const int lane = tid & 31, warp = tid >> 5;
    #pragma unroll
    for (int o = 16; o; o >>= 1) {
        s  += __shfl_xor_sync(0xffffffffu, s,  o);
        sq += __shfl_xor_sync(0xffffffffu, sq, o);
    }
    __shared__ float ss[4], ssq[4];
    if (lane == 0) { ss[warp] = s; ssq[warp] = sq; }
    __syncthreads();
    s  = ss[0]  + ss[1]  + ss[2]  + ss[3];
    sq = ssq[0] + ssq[1] + ssq[2] + ssq[3];

    const float mu  = s  * (1.0f / DIM);
    const float var = sq * (1.0f / DIM) - mu * mu;
    const float r   = rsqrtf(var + 1e-5f);

    const float4 gv = reinterpret_cast<const float4*>(g)[tid];
    const float4 bv = reinterpret_cast<const float4*>(b)[tid];
    float o0 = (v.x - mu) * r * gv.x + bv.x;
    float o1 = (v.y - mu) * r * gv.y + bv.y;
    float o2 = (v.z - mu) * r * gv.z + bv.z;
    float o3 = (v.w - mu) * r * gv.w + bv.w;

    bf16 h0,h1,h2,h3,l0,l1,l2,l3;
    split2(o0, h0, l0); split2(o1, h1, l1);
    split2(o2, h2, l2); split2(o3, h3, l3);
    const size_t o = (size_t)row * DIM + tid * 4;
    reinterpret_cast<__nv_bfloat162*>(&h_hi[o])[0] = __halves2bfloat162(h0, h1);
    reinterpret_cast<__nv_bfloat162*>(&h_hi[o])[1] = __halves2bfloat162(h2, h3);
    reinterpret_cast<__nv_bfloat162*>(&h_lo[o])[0] = __halves2bfloat162(l0, l1);
    reinterpret_cast<__nv_bfloat162*>(&h_lo[o])[1] = __halves2bfloat162(l2, l3);
}

// ---------------------------------------------------------------------------
// Tensor-core GEMM (NT), bf16 hi/lo 3-pass, ldmatrix, 2-stage cp.async.
// MINB = min blocks per SM (3 -> co-resident CTAs hide sync bubbles).
// EPI: 0 plain, 1 +aux residual. NT must be even.
// ---------------------------------------------------------------------------
template<int BM, int BN, int BK, int WM, int WN, int EPI, int MINB>
__global__ void __launch_bounds__(WM*WN*32, MINB)
mma_gemm(const bf16* __restrict__ Ah, const bf16* __restrict__ Al, int lda,
         const bf16* __restrict__ Bh, const bf16* __restrict__ Bl, int ldb,
         float* __restrict__ C, int ldc, int K,
         const float* __restrict__ aux, int ldaux)
{
    constexpr int THREADS = WM * WN * 32;
    constexpr int LDSK = BK + 8;
    constexpr int WTM = BM / WM, WTN = BN / WN;
    constexpr int MT = WTM / 16, NT = WTN / 8;
    constexpr int SA = BM * LDSK, SB = BN * LDSK;
    static_assert((NT & 1) == 0, "NT must be even");

    extern __shared__ char dynsmem[];
    bf16* sAbase = reinterpret_cast<bf16*>(dynsmem);            // [2][2][SA]
    bf16* sBbase = reinterpret_cast<bf16*>(dynsmem) + 4 * SA;   // [2][2][SB]

    const int tid  = threadIdx.x;
    const int wid  = tid >> 5, lane = tid & 31;
    const int wm   = (wid % WM) * WTM;
    const int wn   = (wid / WM) * WTN;
    const int gr   = lane >> 2, tg = lane & 3;
    const int rowBase = blockIdx.y * BM;
    const int colBase = blockIdx.x * BN;

    const unsigned aoff = (unsigned)(((lane & 15) * LDSK + (lane >> 4) * 8) * 2);
    const unsigned boff = (unsigned)((((lane & 7) + ((lane >> 4) & 1) * 8) * LDSK
                                      + ((lane >> 3) & 1) * 8) * 2);

    float acc[MT][NT][4];
    #pragma unroll
    for (int i = 0; i < MT; i++)
        #pragma unroll
        for (int j = 0; j < NT; j++)
            #pragma unroll
            for (int q = 0; q < 4; q++) acc[i][j][q] = 0.0f;

    auto prefetch = [&](int stage, int k0) {
        bf16* dAh = sAbase + (stage * 2 + 0) * SA;
        bf16* dAl = sAbase + (stage * 2 + 1) * SA;
        for (int idx = tid; idx < BM * (BK / 8); idx += THREADS) {
            const int r = idx / (BK / 8), kc = idx % (BK / 8);
            const size_t go = (size_t)(rowBase + r) * lda + k0 + kc * 8;
            cp16(&dAh[r * LDSK + kc * 8], &Ah[go]);
            cp16(&dAl[r * LDSK + kc * 8], &Al[go]);
        }
        bf16* dBh = sBbase + (stage * 2 + 0) * SB;
        bf16* dBl = sBbase + (stage * 2 + 1) * SB;
        for (int idx = tid; idx < BN * (BK / 8); idx += THREADS) {
            const int r = idx / (BK / 8), kc = idx % (BK / 8);
            const size_t go = (size_t)(colBase + r) * ldb + k0 + kc * 8;
            cp16(&dBh[r * LDSK + kc * 8], &Bh[go]);
            cp16(&dBl[r * LDSK + kc * 8], &Bl[go]);
        }
        cp_commit();
    };

    prefetch(0, 0);

    const int NSTEP = K / BK;
    int bufc = 0;
    for (int step = 0; step < NSTEP; step++) {
        cp_wait0();
        __syncthreads();
        if (step + 1 < NSTEP) prefetch(bufc ^ 1, (step + 1) * BK);

        const unsigned baseAh = (unsigned)__cvta_generic_to_shared(
            sAbase + (bufc * 2 + 0) * SA) + (unsigned)(wm * LDSK * 2) + aoff;
        const unsigned baseAl = baseAh + (unsigned)(SA * 2);
        const unsigned baseBh = (unsigned)__cvta_generic_to_shared(
            sBbase + (bufc * 2 + 0) * SB) + (unsigned)(wn * LDSK * 2) + boff;
        const unsigned baseBl = baseBh + (unsigned)(SB * 2);

        #pragma unroll
        for (int kk = 0; kk < BK; kk += 16) {
            unsigned bh[NT][2], bl[NT][2];
            #pragma unroll
            for (int ntp = 0; ntp < NT / 2; ntp++) {
                const unsigned off = (unsigned)((ntp * 16 * LDSK + kk) * 2);
                ldsm_x4(bh[2*ntp][0], bh[2*ntp][1], bh[2*ntp+1][0], bh[2*ntp+1][1],
                        baseBh + off);
                ldsm_x4(bl[2*ntp][0], bl[2*ntp][1], bl[2*ntp+1][0], bl[2*ntp+1][1],
                        baseBl + off);
            }
            unsigned ah[MT][4], al[MT][4];
            #pragma unroll
            for (int mt = 0; mt < MT; mt++) {
                const unsigned off = (unsigned)((mt * 16 * LDSK + kk) * 2);
                ldsm_x4(ah[mt][0], ah[mt][1], ah[mt][2], ah[mt][3], baseAh + off);
                ldsm_x4(al[mt][0], al[mt][1], al[mt][2], al[mt][3], baseAl + off);
            }
            #pragma unroll
            for (int mt = 0; mt < MT; mt++)
                #pragma unroll
                for (int nt = 0; nt < NT; nt++)
                    mma_bf16(acc[mt][nt], ah[mt][0],ah[mt][1],ah[mt][2],ah[mt][3],
                             bh[nt][0], bh[nt][1]);
            #pragma unroll
            for (int mt = 0; mt < MT; mt++)
                #pragma unroll
                for (int nt = 0; nt < NT; nt++)
                    mma_bf16(acc[mt][nt], ah[mt][0],ah[mt][1],ah[mt][2],ah[mt][3],
                             bl[nt][0], bl[nt][1]);
            #pragma unroll
            for (int mt = 0; mt < MT; mt++)
                #pragma unroll
                for (int nt = 0; nt < NT; nt++)
                    mma_bf16(acc[mt][nt], al[mt][0],al[mt][1],al[mt][2],al[mt][3],
                             bh[nt][0], bh[nt][1]);
        }
        __syncthreads();
        bufc ^= 1;
    }

    #pragma unroll
    for (int mt = 0; mt < MT; mt++) {
        #pragma unroll
        for (int nt = 0; nt < NT; nt++) {
            const int r0 = rowBase + wm + mt * 16 + gr;
            const int c0 = colBase + wn + nt * 8 + tg * 2;
            float2 v0 = make_float2(acc[mt][nt][0], acc[mt][nt][1]);
            float2 v1 = make_float2(acc[mt][nt][2], acc[mt][nt][3]);
            if (EPI == 1) {
                const float2 a0 = *reinterpret_cast<const float2*>(
                    &aux[(size_t)r0 * ldaux + c0]);
                const float2 a1 = *reinterpret_cast<const float2*>(
                    &aux[(size_t)(r0 + 8) * ldaux + c0]);
                v0.x += a0.x; v0.y += a0.y;
                v1.x += a1.x; v1.y += a1.y;
            }
            *reinterpret_cast<float2*>(&C[(size_t)r0 * ldc + c0])       = v0;
            *reinterpret_cast<float2*>(&C[(size_t)(r0 + 8) * ldc + c0]) = v1;
        }
    }
}

// ---------------------------------------------------------------------------
// Plain fp32 SIMT GEMM (tiny dt projection, K=32). EPI2 = softplus(acc+aux[c])
// ---------------------------------------------------------------------------
template<int BM, int BN, int BK, int TM, int TN, int EPI>
__global__ void __launch_bounds__((BM/TM)*(BN/TN))
gemm_nt(const float* __restrict__ A, int lda,
        const float* __restrict__ B, int ldb,
        float* __restrict__ C, int ldc,
        int K,
        const float* __restrict__ aux, int ldaux)
{
    constexpr int THREADS = (BM/TM)*(BN/TN);
    constexpr int KQ = BK / 4;
    constexpr int A_LOADS = (BM*BK) / (4*THREADS);
    constexpr int B_LOADS = (BN*BK) / (4*THREADS);

    __shared__ float As[BK][BM + 4];
    __shared__ float Bs[BK][BN + 4];

    const int tid = threadIdx.x;
    const int tx  = tid % (BN/TN);
    const int ty  = tid / (BN/TN);
    const int rowBase = blockIdx.y * BM;
    const int colBase = blockIdx.x * BN;

    float acc[TM][TN];
    #pragma unroll
    for (int i = 0; i < TM; i++)
        #pragma unroll
        for (int j = 0; j < TN; j++) acc[i][j] = 0.0f;

    for (int k0 = 0; k0 < K; k0 += BK) {
        #pragma unroll
        for (int i = 0; i < A_LOADS; i++) {
            const int idx = tid + i * THREADS;
            const int r = idx / KQ, kq = idx % KQ;
            const float4 v = *reinterpret_cast<const float4*>(
                &A[(size_t)(rowBase + r) * lda + k0 + kq * 4]);
            As[kq*4+0][r] = v.x; As[kq*4+1][r] = v.y;
            As[kq*4+2][r] = v.z; As[kq*4+3][r] = v.w;
        }
        #pragma unroll
        for (int i = 0; i < B_LOADS; i++) {
            const int idx = tid + i * THREADS;
            const int r = idx / KQ, kq = idx % KQ;
            const float4 v = *reinterpret_cast<const float4*>(
                &B[(size_t)(colBase + r) * ldb + k0 + kq * 4]);
            Bs[kq*4+0][r] = v.x; Bs[kq*4+1][r] = v.y;
            Bs[kq*4+2][r] = v.z; Bs[kq*4+3][r] = v.w;
        }
        __syncthreads();

        #pragma unroll
        for (int kk = 0; kk < BK; kk++) {
            float ra[TM], rb[TN];
            #pragma unroll
            for (int i = 0; i < TM; i++) ra[i] = As[kk][ty*TM + i];
            #pragma unroll
            for (int j = 0; j < TN; j++) rb[j] = Bs[kk][tx*TN + j];
            #pragma unroll
            for (int i = 0; i < TM; i++)
                #pragma unroll
                for (int j = 0; j < TN; j++)
                    acc[i][j] = fmaf(ra[i], rb[j], acc[i][j]);
        }
        __syncthreads();
    }

    #pragma unroll
    for (int i = 0; i < TM; i++) {
        const int r = rowBase + ty*TM + i;
        #pragma unroll
        for (int j = 0; j < TN; j++) {
            const int c = colBase + tx*TN + j;
            float v = acc[i][j];
            if (EPI == 2) v = softplus_f(v + aux[c]);
            C[(size_t)r * ldc + c] = v;
        }
    }
}

// ---------------------------------------------------------------------------
// Depthwise causal conv + bias + SiLU; 4 timesteps x 4 channels per thread.
// ---------------------------------------------------------------------------
__global__ void conv_silu_kernel(const float* __restrict__ xz,
                                 const float* __restrict__ conv_w,
                                 const float* __restrict__ conv_b,
                                 float* __restrict__ xc,
                                 bf16* __restrict__ xc_hi,
                                 bf16* __restrict__ xc_lo)
{
    const int t  = blockIdx.x * blockDim.x + threadIdx.x;
    const int dq = t & (D_INNER/4 - 1);
    const int rg = t / (D_INNER/4);
    const int l0 = (rg & (SEQ/4 - 1)) * 4;
    const int b  = rg / (SEQ/4);
    const int d0 = dq * 4;

    float4 cw[4];
    #pragma unroll
    for (int i = 0; i < 4; i++)
        cw[i] = *reinterpret_cast<const float4*>(&conv_w[(d0 + i) * D_CONV]);
    const float4 bias = *reinterpret_cast<const float4*>(&conv_b[d0]);

    float4 xv[7];
    #pragma unroll
    for (int k = 0; k < 7; k++) {
        const int ls = l0 - 3 + k;
        if (ls >= 0)
            xv[k] = *reinterpret_cast<const float4*>(
                &xz[((size_t)(b * SEQ + ls)) * (2 * D_INNER) + d0]);
        else
            xv[k] = make_float4(0.f, 0.f, 0.f, 0.f);
    }

    #pragma unroll
    for (int u = 0; u < 4; u++) {
        float4 a;
        a.x = fmaf(xv[u].x,   cw[0].x, fmaf(xv[u+1].x, cw[0].y,
              fmaf(xv[u+2].x, cw[0].z, fmaf(xv[u+3].x, cw[0].w, bias.x))));
        a.y = fmaf(xv[u].y,   cw[1].x, fmaf(xv[u+1].y, cw[1].y,
              fmaf(xv[u+2].y, cw[1].z, fmaf(xv[u+3].y, cw[1].w, bias.y))));
        a.z = fmaf(xv[u].z,   cw[2].x, fmaf(xv[u+1].z, cw[2].y,
              fmaf(xv[u+2].z, cw[2].z, fmaf(xv[u+3].z, cw[2].w, bias.z))));
        a.w = fmaf(xv[u].w,   cw[3].x, fmaf(xv[u+1].w, cw[3].y,
              fmaf(xv[u+2].w, cw[3].z, fmaf(xv[u+3].w, cw[3].w, bias.w))));

        float4 o;
        o.x = a.x / (1.0f + __expf(-a.x));
        o.y = a.y / (1.0f + __expf(-a.y));
        o.z = a.z / (1.0f + __expf(-a.z));
        o.w = a.w / (1.0f + __expf(-a.w));

        const size_t off = ((size_t)(b * SEQ + l0 + u)) * D_INNER + d0;
        *reinterpret_cast<float4*>(&xc[off]) = o;

        bf16 h0,h1,h2,h3,l0b,l1b,l2b,l3b;
        split2(o.x, h0, l0b); split2(o.y, h1, l1b);
        split2(o.z, h2, l2b); split2(o.w, h3, l3b);
        reinterpret_cast<__nv_bfloat162*>(&xc_hi[off])[0] = __halves2bfloat162(h0, h1);
        reinterpret_cast<__nv_bfloat162*>(&xc_hi[off])[1] = __halves2bfloat162(h2, h3);
        reinterpret_cast<__nv_bfloat162*>(&xc_lo[off])[0] = __halves2bfloat162(l0b, l1b);
        reinterpret_cast<__nv_bfloat162*>(&xc_lo[off])[1] = __halves2bfloat162(l2b, l3b);
    }
}

// ---------------------------------------------------------------------------
// Chunked parallel scan (R5 structure, proven).
// ---------------------------------------------------------------------------
__global__ void __launch_bounds__(256)
scanA_kernel(const float* __restrict__ dt,
             const float* __restrict__ proj,
             const float* __restrict__ xc,
             const float* __restrict__ A_log,
             float* __restrict__ P,
             float* __restrict__ q)
{
    const int ch = blockIdx.x & (CH - 1);
    const int bg = blockIdx.x / CH;
    const int b  = bg >> 6, g = bg & 63;
    const int d0 = g * 16;
    const int tid = threadIdx.x;
    const int c = tid >> 4, n = tid & 15;
    const int d = d0 + c;

    __shared__ float sdt[64][16], sxc[64][16], sB[64][16];

    const float Av = -__expf(A_log[d * D_STATE + n]);
    const size_t rowb = (size_t)b * SEQ + ch * CLEN;
    const int lt = tid >> 2, lq = tid & 3;

    float s = 0.0f, dtsum = 0.0f;

    for (int t0 = 0; t0 < CLEN; t0 += 64) {
        __syncthreads();
        {
            const size_t row = rowb + t0 + lt;
            *reinterpret_cast<float4*>(&sdt[lt][lq*4]) =
                *reinterpret_cast<const float4*>(&dt[row * D_INNER + d0 + lq*4]);
            *reinterpret_cast<float4*>(&sxc[lt][lq*4]) =
                *reinterpret_cast<const float4*>(&xc[row * D_INNER + d0 + lq*4]);
            *reinterpret_cast<float4*>(&sB[lt][lq*4]) =
                *reinterpret_cast<const float4*>(&proj[row * 64 + DT_RANK + lq*4]);
        }
        __syncthreads();

        #pragma unroll 8
        for (int t = 0; t < 64; t++) {
            const float dtv = sdt[t][c];
            const float dA  = __expf(dtv * Av);
            s = fmaf(s, dA, dtv * sB[t][n] * sxc[t][c]);
            dtsum += dtv;
        }
    }
    P[(size_t)blockIdx.x * 256 + tid] = __expf(Av * dtsum);
    q[(size_t)blockIdx.x * 256 + tid] = s;
}

__global__ void __launch_bounds__(256)
scanB_kernel(const float* __restrict__ P,
             const float* __restrict__ q,
             float* __restrict__ sin)
{
    const int tid = threadIdx.x;
    float s = 0.0f;
    #pragma unroll
    for (int ch = 0; ch < CH; ch++) {
        const size_t idx = ((size_t)blockIdx.x * CH + ch) * 256 + tid;
        sin[idx] = s;
        s = fmaf(P[idx], s, q[idx]);
    }
}

__global__ void __launch_bounds__(256)
scanC_kernel(const float* __restrict__ dt,
             const float* __restrict__ proj,
             const float* __restrict__ xc,
             const float* __restrict__ xz,
             const float* __restrict__ A_log,
             const float* __restrict__ Dp,
             const float* __restrict__ sin,
             bf16* __restrict__ y_hi,
             bf16* __restrict__ y_lo)
{
    const int ch = blockIdx.x & (CH - 1);
    const int bg = blockIdx.x / CH;
    const int b  = bg >> 6, g = bg & 63;
    const int d0 = g * 16;
    const int tid = threadIdx.x;
    const int c = tid >> 4, n = tid & 15;
    const int d = d0 + c;

    __shared__ float sdt[64][16], sxc[64][16], sz[64][16];
    __shared__ float sBC[64][32];
    __shared__ float sy [64][16];

    const float Av = -__expf(A_log[d * D_STATE + n]);
    const float Dv = Dp[d];
    const size_t rowb = (size_t)b * SEQ + ch * CLEN;
    const int lt = tid >> 2, lq = tid & 3;

    float s = sin[(size_t)blockIdx.x * 256 + tid];

    for (int t0 = 0; t0 < CLEN; t0 += 64) {
        __syncthreads();
        {
            const size_t row = rowb + t0 + lt;
            *reinterpret_cast<float4*>(&sdt[lt][lq*4]) =
                *reinterpret_cast<const float4*>(&dt[row * D_INNER + d0 + lq*4]);
            *reinterpret_cast<float4*>(&sxc[lt][lq*4]) =
                *reinterpret_cast<const float4*>(&xc[row * D_INNER + d0 + lq*4]);
            *reinterpret_cast<float4*>(&sz[lt][lq*4]) =
                *reinterpret_cast<const float4*>(
                    &xz[row * 2 * D_INNER + D_INNER + d0 + lq*4]);
            *reinterpret_cast<float4*>(&sBC[lt][lq*4]) =
                *reinterpret_cast<const float4*>(&proj[row * 64 + DT_RANK + lq*4]);
            *reinterpret_cast<float4*>(&sBC[lt][16 + lq*4]) =
                *reinterpret_cast<const float4*>(
                    &proj[row * 64 + DT_RANK + D_STATE + lq*4]);
        }
        __syncthreads();

        #pragma unroll 8
        for (int t = 0; t < 64; t++) {
            const float dtv = sdt[t][c];
            const float xcv = sxc[t][c];
            const float dA  = __expf(dtv * Av);
            s = fmaf(s, dA, dtv * sBC[t][n] * xcv);
            float part = s * sBC[t][16 + n];
            part += __shfl_xor_sync(0xffffffffu, part, 8);
            part += __shfl_xor_sync(0xffffffffu, part, 4);
            part += __shfl_xor_sync(0xffffffffu, part, 2);
            part += __shfl_xor_sync(0xffffffffu, part, 1);
            if (n == 0) {
                const float zz = sz[t][c];
                sy[t][c] = (part + xcv * Dv) * (zz / (1.0f + __expf(-zz)));
            }
        }
        __syncthreads();
        {
            const float4 v = *reinterpret_cast<const float4*>(&sy[lt][lq*4]);
            const size_t o = (rowb + t0 + lt) * D_INNER + d0 + lq*4;
            bf16 h0,h1,h2,h3,l0,l1,l2,l3;
            split2(v.x, h0, l0); split2(v.y, h1, l1);
            split2(v.z, h2, l2); split2(v.w, h3, l3);
            reinterpret_cast<__nv_bfloat162*>(&y_hi[o])[0] = __halves2bfloat162(h0, h1);
            reinterpret_cast<__nv_bfloat162*>(&y_hi[o])[1] = __halves2bfloat162(h2, h3);
            reinterpret_cast<__nv_bfloat162*>(&y_lo[o])[0] = __halves2bfloat162(l0, l1);
            reinterpret_cast<__nv_bfloat162*>(&y_lo[o])[1] = __halves2bfloat162(l2, l3);
        }
    }
}

// ---------------------------------------------------------------------------
// Launch sequence
// ---------------------------------------------------------------------------
extern "C" void kernel_launch(void* const* d_in, const int* in_sizes, int n_in,
                              void* d_out, int out_size)
{
    const float* x      = (const float*)d_in[0];
    const float* ln_g   = (const float*)d_in[1];
    const float* ln_b   = (const float*)d_in[2];
    const float* W_in   = (const float*)d_in[3];
    const float* conv_w = (const float*)d_in[4];
    const float* conv_b = (const float*)d_in[5];
    const float* W_xprj = (const float*)d_in[6];
    const float* W_dt   = (const float*)d_in[7];
    const float* b_dt   = (const float*)d_in[8];
    const float* A_log  = (const float*)d_in[9];
    const float* Dp     = (const float*)d_in[10];
    const float* W_out  = (const float*)d_in[11];
    float* out = (float*)d_out;

    float *p_xz, *p_xc, *p_proj, *p_dt, *p_P, *p_q, *p_sin;
    bf16 *p_hh, *p_hl, *p_xch, *p_xcl, *p_yh, *p_yl;
    bf16 *p_wih, *p_wil, *p_wxh, *p_wxl, *p_woh, *p_wol;
    cudaGetSymbolAddress((void**)&p_xz,   g_xz);
    cudaGetSymbolAddress((void**)&p_xc,   g_xc);
    cudaGetSymbolAddress((void**)&p_proj, g_proj);
    cudaGetSymbolAddress((void**)&p_dt,   g_dt);
    cudaGetSymbolAddress((void**)&p_P,    g_P);
    cudaGetSymbolAddress((void**)&p_q,    g_q);
    cudaGetSymbolAddress((void**)&p_sin,  g_sin);
    cudaGetSymbolAddress((void**)&p_hh,   g_h_hi);
    cudaGetSymbolAddress((void**)&p_hl,   g_h_lo);
    cudaGetSymbolAddress((void**)&p_xch,  g_xc_hi);
    cudaGetSymbolAddress((void**)&p_xcl,  g_xc_lo);
    cudaGetSymbolAddress((void**)&p_yh,   g_y_hi);
    cudaGetSymbolAddress((void**)&p_yl,   g_y_lo);
    cudaGetSymbolAddress((void**)&p_wih,  g_Win_hi);
    cudaGetSymbolAddress((void**)&p_wil,  g_Win_lo);
    cudaGetSymbolAddress((void**)&p_wxh,  g_Wxp_hi);
    cudaGetSymbolAddress((void**)&p_wxl,  g_Wxp_lo);
    cudaGetSymbolAddress((void**)&p_woh,  g_Wout_hi);
    cudaGetSymbolAddress((void**)&p_wol,  g_Wout_lo);

    // dyn smem: 2 stages * 2 parts * (SA + SB) bf16 * 2 bytes
    const int smemG1 = 2 * 2 * (128*40 + 64*40) * 2;   // 61440 (128x64)
    const int smemG3 = 2 * 2 * ( 64*40 + 64*40) * 2;   // 40960 (64x64)
    const int smemP  = 2 * 2 * ( 32*40 + 64*40) * 2;   // 30720
    cudaFuncSetAttribute((const void*)mma_gemm<128,64,32,2,4,0,3>,
                         cudaFuncAttributeMaxDynamicSharedMemorySize, smemG1);
    cudaFuncSetAttribute((const void*)mma_gemm<64,64,32,2,4,1,3>,
                         cudaFuncAttributeMaxDynamicSharedMemorySize, smemG3);
    cudaFuncSetAttribute((const void*)mma_gemm<32,64,32,2,4,0,3>,
                         cudaFuncAttributeMaxDynamicSharedMemorySize, smemP);

    // 0. weight splits (two launches -> gemm1 is launch #4 for the profiler)
    split_win_kernel<<<(N4_WIN + 255)/256, 256>>>(W_in, p_wih, p_wil);
    split_rest_kernel<<<(N4_WXP + N4_WOUT + 255)/256, 256>>>(
        W_xprj, W_out, p_wxh, p_wxl, p_woh, p_wol);

    // 1. LayerNorm (+ split)
    ln_kernel<<<MROWS, 128>>>(x, ln_g, ln_b, p_hh, p_hl);

    // 2. xz = h @ W_in^T    (4096 x 2048 x 512)  tensor cores, 3 CTA/SM
    mma_gemm<128,64,32,2,4,0,3><<<dim3(2*D_INNER/64, MROWS/128), 256, smemG1>>>(
        p_hh, p_hl, DIM, p_wih, p_wil, DIM, p_xz, 2*D_INNER, DIM, nullptr, 0);

    // 3. conv + silu (+ split), 4x4 blocked
    conv_silu_kernel<<<(MROWS/4) * (D_INNER/4) / 256, 256>>>(
        p_xz, conv_w, conv_b, p_xc, p_xch, p_xcl);

    // 4. proj = xc @ W_xproj^T (4096 x 64 x 1024)  tensor cores
    mma_gemm<32,64,32,2,4,0,3><<<dim3(1, MROWS/32), 256, smemP>>>(
        p_xch, p_xcl, D_INNER, p_wxh, p_wxl, D_INNER, p_proj, 64, D_INNER,
        nullptr, 0);

    // 5. dt = softplus(proj[:, :32] @ W_dt^T + b_dt)  (4096 x 1024 x 32) SIMT
    gemm_nt<64,64,16,4,4,2><<<dim3(D_INNER/64, MROWS/64), 256>>>(
        p_proj, 64, W_dt, DT_RANK, p_dt, D_INNER, DT_RANK, b_dt, 0);

    // 6. SSM scan (chunk-parallel, 3 phases) + gating (+ split of y)
    scanA_kernel<<<BATCH * 64 * CH, 256>>>(p_dt, p_proj, p_xc, A_log, p_P, p_q);
    scanB_kernel<<<BATCH * 64, 256>>>(p_P, p_q, p_sin);
    scanC_kernel<<<BATCH * 64 * CH, 256>>>(
        p_dt, p_proj, p_xc, p_xz, A_log, Dp, p_sin, p_yh, p_yl);

    // 7. out = y @ W_out^T + x (4096 x 512 x 1024)  64x64 tiles -> 512 CTAs
    mma_gemm<64,64,32,2,4,1,3><<<dim3(DIM/64, MROWS/64), 256, smemG3>>>(
        p_yh, p_yl, D_INNER, p_woh, p_wol, D_INNER, out, DIM, D_INNER, x, DIM);
}

// round 17
// speedup vs baseline: 1.0445x; 1.0445x over previous
#include <cuda_runtime.h>
#include <cuda_bf16.h>
#include <math.h>

// Problem constants
#define BATCH   2
#define SEQ     2048
#define DIM     512
#define D_INNER 1024
#define D_STATE 16
#define D_CONV  4
#define DT_RANK 32
#define MROWS   (BATCH * SEQ)          // 4096
#define CH      8                      // scan chunks
#define CLEN    (SEQ / CH)             // 256

typedef __nv_bfloat16 bf16;

// ---------------------------------------------------------------------------
// Scratch (static device arrays; no allocation allowed)
// ---------------------------------------------------------------------------
__device__ float g_xz  [MROWS * 2 * D_INNER];
__device__ float g_xc  [MROWS * D_INNER];
__device__ float g_proj[MROWS * 64];
__device__ float g_dt  [MROWS * D_INNER];

__device__ float g_P  [BATCH * 64 * CH * 256];
__device__ float g_q  [BATCH * 64 * CH * 256];
__device__ float g_sin[BATCH * 64 * CH * 256];

__device__ bf16 g_h_hi [MROWS * DIM],      g_h_lo [MROWS * DIM];
__device__ bf16 g_xc_hi[MROWS * D_INNER],  g_xc_lo[MROWS * D_INNER];
__device__ bf16 g_y_hi [MROWS * D_INNER],  g_y_lo [MROWS * D_INNER];
__device__ bf16 g_Win_hi [2 * D_INNER * DIM], g_Win_lo [2 * D_INNER * DIM];
__device__ bf16 g_Wxp_hi [64 * D_INNER],      g_Wxp_lo [64 * D_INNER];
__device__ bf16 g_Wout_hi[DIM * D_INNER],     g_Wout_lo[DIM * D_INNER];

// ---------------------------------------------------------------------------
// Helpers
// ---------------------------------------------------------------------------
__device__ __forceinline__ void split2(float x, bf16& h, bf16& l)
{
    h = __float2bfloat16(x);
    l = __float2bfloat16(x - __bfloat162float(h));
}

__device__ __forceinline__ float softplus_f(float x)
{
    return (x > 20.0f) ? x : log1pf(__expf(x));
}

__device__ __forceinline__ void mma_bf16(float* d,
                                         unsigned a0, unsigned a1,
                                         unsigned a2, unsigned a3,
                                         unsigned b0, unsigned b1)
{
    asm volatile(
        "mma.sync.aligned.m16n8k16.row.col.f32.bf16.bf16.f32 "
        "{%0,%1,%2,%3},{%4,%5,%6,%7},{%8,%9},{%0,%1,%2,%3};"
        : "+f"(d[0]), "+f"(d[1]), "+f"(d[2]), "+f"(d[3])
        : "r"(a0), "r"(a1), "r"(a2), "r"(a3), "r"(b0), "r"(b1));
}

__device__ __forceinline__ void ldsm_x4(unsigned& r0, unsigned& r1,
                                        unsigned& r2, unsigned& r3,
                                        unsigned saddr)
{
    asm volatile("ldmatrix.sync.aligned.m8n8.x4.shared.b16 {%0,%1,%2,%3}, [%4];"
                 : "=r"(r0), "=r"(r1), "=r"(r2), "=r"(r3) : "r"(saddr));
}

__device__ __forceinline__ void cp16(void* smem_dst, const void* gmem_src)
{
    const unsigned sa = (unsigned)__cvta_generic_to_shared(smem_dst);
    asm volatile("cp.async.cg.shared.global [%0], [%1], 16;"
                 :: "r"(sa), "l"(gmem_src));
}
__device__ __forceinline__ void cp_commit()
{
    asm volatile("cp.async.commit_group;");
}
__device__ __forceinline__ void cp_wait0()
{
    asm volatile("cp.async.wait_group 0;");
}

// ---------------------------------------------------------------------------
// Merged prep kernel: LN (blocks 0..2047, 2 rows each) + all weight splits
// (blocks 2048..). One launch replaces three.
// ---------------------------------------------------------------------------
#define N4_WIN  (2 * D_INNER * DIM / 4)     // 262144
#define N4_WXP  (64 * D_INNER / 4)          // 16384
#define N4_WOUT (DIM * D_INNER / 4)         // 131072
#define N4_ALL  (N4_WIN + N4_WXP + N4_WOUT) // 409600
#define LN_BLOCKS   (MROWS / 2)             // 2048
#define SPLIT_BLOCKS ((N4_ALL + 255) / 256) // 1600

__global__ void __launch_bounds__(256)
prep_kernel(const float* __restrict__ x,
            const float* __restrict__ g,
            const float* __restrict__ b,
            const float* __restrict__ W_in,
            const float* __restrict__ W_xp,
            const float* __restrict__ W_out,
            bf16* __restrict__ h_hi, bf16* __restrict__ h_lo,
            bf16* __restrict__ wih, bf16* __restrict__ wil,
            bf16* __restrict__ wxh, bf16* __restrict__ wxl,
            bf16* __restrict__ woh, bf16* __restrict__ wol)
{
    const int tid = threadIdx.x;
    if (blockIdx.x < LN_BLOCKS) {
        // ---- LayerNorm: 2 rows per block, 128 threads per row ----
        const int half = tid >> 7;             // 0 or 1
        const int wt   = tid & 127;            // thread within row
        const int row  = blockIdx.x * 2 + half;
        const float4 v = reinterpret_cast<const float4*>(
            x + (size_t)row * DIM)[wt];

        float s  = v.x + v.y + v.z + v.w;
        float sq = v.x*v.x + v.y*v.y + v.z*v.z + v.w*v.w;

        const int lane = tid & 31;
        const int wrp  = (tid >> 5) & 3;       // warp within row half
        #pragma unroll
        for (int o = 16; o; o >>= 1) {
            s  += __shfl_xor_sync(0xffffffffu, s,  o);
            sq += __shfl_xor_sync(0xffffffffu, sq, o);
        }
        __shared__ float ss[2][4], ssq[2][4];
        if (lane == 0) { ss[half][wrp] = s; ssq[half][wrp] = sq; }
        __syncthreads();
        s  = ss[half][0]  + ss[half][1]  + ss[half][2]  + ss[half][3];
        sq = ssq[half][0] + ssq[half][1] + ssq[half][2] + ssq[half][3];

        const float mu  = s  * (1.0f / DIM);
        const float var = sq * (1.0f / DIM) - mu * mu;
        const float r   = rsqrtf(var + 1e-5f);

        const float4 gv = reinterpret_cast<const float4*>(g)[wt];
        const float4 bv = reinterpret_cast<const float4*>(b)[wt];
        float o0 = (v.x - mu) * r * gv.x + bv.x;
        float o1 = (v.y - mu) * r * gv.y + bv.y;
        float o2 = (v.z - mu) * r * gv.z + bv.z;
        float o3 = (v.w - mu) * r * gv.w + bv.w;

        bf16 h0,h1,h2,h3,l0,l1,l2,l3;
        split2(o0, h0, l0); split2(o1, h1, l1);
        split2(o2, h2, l2); split2(o3, h3, l3);
        const size_t o = (size_t)row * DIM + wt * 4;
        reinterpret_cast<__nv_bfloat162*>(&h_hi[o])[0] = __halves2bfloat162(h0, h1);
        reinterpret_cast<__nv_bfloat162*>(&h_hi[o])[1] = __halves2bfloat162(h2, h3);
        reinterpret_cast<__nv_bfloat162*>(&h_lo[o])[0] = __halves2bfloat162(l0, l1);
        reinterpret_cast<__nv_bfloat162*>(&h_lo[o])[1] = __halves2bfloat162(l2, l3);
    } else {
        // ---- weight splits ----
        int i = (blockIdx.x - LN_BLOCKS) * 256 + tid;
        const float* src; bf16 *hi, *lo;
        if (i < N4_WIN) {
            src = W_in; hi = wih; lo = wil;
        } else if (i < N4_WIN + N4_WXP) {
            i -= N4_WIN; src = W_xp; hi = wxh; lo = wxl;
        } else if (i < N4_ALL) {
            i -= N4_WIN + N4_WXP; src = W_out; hi = woh; lo = wol;
        } else return;

        const float4 v = reinterpret_cast<const float4*>(src)[i];
        bf16 h0,h1,h2,h3,l0,l1,l2,l3;
        split2(v.x, h0, l0); split2(v.y, h1, l1);
        split2(v.z, h2, l2); split2(v.w, h3, l3);
        reinterpret_cast<__nv_bfloat162*>(hi)[2*i]   = __halves2bfloat162(h0, h1);
        reinterpret_cast<__nv_bfloat162*>(hi)[2*i+1] = __halves2bfloat162(h2, h3);
        reinterpret_cast<__nv_bfloat162*>(lo)[2*i]   = __halves2bfloat162(l0, l1);
        reinterpret_cast<__nv_bfloat162*>(lo)[2*i+1] = __halves2bfloat162(l2, l3);
    }
}

// ---------------------------------------------------------------------------
// Tensor-core GEMM (NT), bf16 hi/lo 3-pass, ldmatrix, 2-stage cp.async.
// MINB = min blocks per SM (3 -> co-resident CTAs hide sync bubbles).
// EPI: 0 plain, 1 +aux residual. NT must be even.
// ---------------------------------------------------------------------------
template<int BM, int BN, int BK, int WM, int WN, int EPI, int MINB>
__global__ void __launch_bounds__(WM*WN*32, MINB)
mma_gemm(const bf16* __restrict__ Ah, const bf16* __restrict__ Al, int lda,
         const bf16* __restrict__ Bh, const bf16* __restrict__ Bl, int ldb,
         float* __restrict__ C, int ldc, int K,
         const float* __restrict__ aux, int ldaux)
{
    constexpr int THREADS = WM * WN * 32;
    constexpr int LDSK = BK + 8;
    constexpr int WTM = BM / WM, WTN = BN / WN;
    constexpr int MT = WTM / 16, NT = WTN / 8;
    constexpr int SA = BM * LDSK, SB = BN * LDSK;
    static_assert((NT & 1) == 0, "NT must be even");

    extern __shared__ char dynsmem[];
    bf16* sAbase = reinterpret_cast<bf16*>(dynsmem);            // [2][2][SA]
    bf16* sBbase = reinterpret_cast<bf16*>(dynsmem) + 4 * SA;   // [2][2][SB]

    const int tid  = threadIdx.x;
    const int wid  = tid >> 5, lane = tid & 31;
    const int wm   = (wid % WM) * WTM;
    const int wn   = (wid / WM) * WTN;
    const int gr   = lane >> 2, tg = lane & 3;
    const int rowBase = blockIdx.y * BM;
    const int colBase = blockIdx.x * BN;

    const unsigned aoff = (unsigned)(((lane & 15) * LDSK + (lane >> 4) * 8) * 2);
    const unsigned boff = (unsigned)((((lane & 7) + ((lane >> 4) & 1) * 8) * LDSK
                                      + ((lane >> 3) & 1) * 8) * 2);

    float acc[MT][NT][4];
    #pragma unroll
    for (int i = 0; i < MT; i++)
        #pragma unroll
        for (int j = 0; j < NT; j++)
            #pragma unroll
            for (int q = 0; q < 4; q++) acc[i][j][q] = 0.0f;

    auto prefetch = [&](int stage, int k0) {
        bf16* dAh = sAbase + (stage * 2 + 0) * SA;
        bf16* dAl = sAbase + (stage * 2 + 1) * SA;
        for (int idx = tid; idx < BM * (BK / 8); idx += THREADS) {
            const int r = idx / (BK / 8), kc = idx % (BK / 8);
            const size_t go = (size_t)(rowBase + r) * lda + k0 + kc * 8;
            cp16(&dAh[r * LDSK + kc * 8], &Ah[go]);
            cp16(&dAl[r * LDSK + kc * 8], &Al[go]);
        }
        bf16* dBh = sBbase + (stage * 2 + 0) * SB;
        bf16* dBl = sBbase + (stage * 2 + 1) * SB;
        for (int idx = tid; idx < BN * (BK / 8); idx += THREADS) {
            const int r = idx / (BK / 8), kc = idx % (BK / 8);
            const size_t go = (size_t)(colBase + r) * ldb + k0 + kc * 8;
            cp16(&dBh[r * LDSK + kc * 8], &Bh[go]);
            cp16(&dBl[r * LDSK + kc * 8], &Bl[go]);
        }
        cp_commit();
    };

    prefetch(0, 0);

    const int NSTEP = K / BK;
    int bufc = 0;
    for (int step = 0; step < NSTEP; step++) {
        cp_wait0();
        __syncthreads();
        if (step + 1 < NSTEP) prefetch(bufc ^ 1, (step + 1) * BK);

        const unsigned baseAh = (unsigned)__cvta_generic_to_shared(
            sAbase + (bufc * 2 + 0) * SA) + (unsigned)(wm * LDSK * 2) + aoff;
        const unsigned baseAl = baseAh + (unsigned)(SA * 2);
        const unsigned baseBh = (unsigned)__cvta_generic_to_shared(
            sBbase + (bufc * 2 + 0) * SB) + (unsigned)(wn * LDSK * 2) + boff;
        const unsigned baseBl = baseBh + (unsigned)(SB * 2);

        #pragma unroll
        for (int kk = 0; kk < BK; kk += 16) {
            unsigned bh[NT][2], bl[NT][2];
            #pragma unroll
            for (int ntp = 0; ntp < NT / 2; ntp++) {
                const unsigned off = (unsigned)((ntp * 16 * LDSK + kk) * 2);
                ldsm_x4(bh[2*ntp][0], bh[2*ntp][1], bh[2*ntp+1][0], bh[2*ntp+1][1],
                        baseBh + off);
                ldsm_x4(bl[2*ntp][0], bl[2*ntp][1], bl[2*ntp+1][0], bl[2*ntp+1][1],
                        baseBl + off);
            }
            unsigned ah[MT][4], al[MT][4];
            #pragma unroll
            for (int mt = 0; mt < MT; mt++) {
                const unsigned off = (unsigned)((mt * 16 * LDSK + kk) * 2);
                ldsm_x4(ah[mt][0], ah[mt][1], ah[mt][2], ah[mt][3], baseAh + off);
                ldsm_x4(al[mt][0], al[mt][1], al[mt][2], al[mt][3], baseAl + off);
            }
            #pragma unroll
            for (int mt = 0; mt < MT; mt++)
                #pragma unroll
                for (int nt = 0; nt < NT; nt++)
                    mma_bf16(acc[mt][nt], ah[mt][0],ah[mt][1],ah[mt][2],ah[mt][3],
                             bh[nt][0], bh[nt][1]);
            #pragma unroll
            for (int mt = 0; mt < MT; mt++)
                #pragma unroll
                for (int nt = 0; nt < NT; nt++)
                    mma_bf16(acc[mt][nt], ah[mt][0],ah[mt][1],ah[mt][2],ah[mt][3],
                             bl[nt][0], bl[nt][1]);
            #pragma unroll
            for (int mt = 0; mt < MT; mt++)
                #pragma unroll
                for (int nt = 0; nt < NT; nt++)
                    mma_bf16(acc[mt][nt], al[mt][0],al[mt][1],al[mt][2],al[mt][3],
                             bh[nt][0], bh[nt][1]);
        }
        __syncthreads();
        bufc ^= 1;
    }

    #pragma unroll
    for (int mt = 0; mt < MT; mt++) {
        #pragma unroll
        for (int nt = 0; nt < NT; nt++) {
            const int r0 = rowBase + wm + mt * 16 + gr;
            const int c0 = colBase + wn + nt * 8 + tg * 2;
            float2 v0 = make_float2(acc[mt][nt][0], acc[mt][nt][1]);
            float2 v1 = make_float2(acc[mt][nt][2], acc[mt][nt][3]);
            if (EPI == 1) {
                const float2 a0 = *reinterpret_cast<const float2*>(
                    &aux[(size_t)r0 * ldaux + c0]);
                const float2 a1 = *reinterpret_cast<const float2*>(
                    &aux[(size_t)(r0 + 8) * ldaux + c0]);
                v0.x += a0.x; v0.y += a0.y;
                v1.x += a1.x; v1.y += a1.y;
            }
            *reinterpret_cast<float2*>(&C[(size_t)r0 * ldc + c0])       = v0;
            *reinterpret_cast<float2*>(&C[(size_t)(r0 + 8) * ldc + c0]) = v1;
        }
    }
}

// ---------------------------------------------------------------------------
// Plain fp32 SIMT GEMM (tiny dt projection, K=32). EPI2 = softplus(acc+aux[c])
// ---------------------------------------------------------------------------
template<int BM, int BN, int BK, int TM, int TN, int EPI>
__global__ void __launch_bounds__((BM/TM)*(BN/TN))
gemm_nt(const float* __restrict__ A, int lda,
        const float* __restrict__ B, int ldb,
        float* __restrict__ C, int ldc,
        int K,
        const float* __restrict__ aux, int ldaux)
{
    constexpr int THREADS = (BM/TM)*(BN/TN);
    constexpr int KQ = BK / 4;
    constexpr int A_LOADS = (BM*BK) / (4*THREADS);
    constexpr int B_LOADS = (BN*BK) / (4*THREADS);

    __shared__ float As[BK][BM + 4];
    __shared__ float Bs[BK][BN + 4];

    const int tid = threadIdx.x;
    const int tx  = tid % (BN/TN);
    const int ty  = tid / (BN/TN);
    const int rowBase = blockIdx.y * BM;
    const int colBase = blockIdx.x * BN;

    float acc[TM][TN];
    #pragma unroll
    for (int i = 0; i < TM; i++)
        #pragma unroll
        for (int j = 0; j < TN; j++) acc[i][j] = 0.0f;

    for (int k0 = 0; k0 < K; k0 += BK) {
        #pragma unroll
        for (int i = 0; i < A_LOADS; i++) {
            const int idx = tid + i * THREADS;
            const int r = idx / KQ, kq = idx % KQ;
            const float4 v = *reinterpret_cast<const float4*>(
                &A[(size_t)(rowBase + r) * lda + k0 + kq * 4]);
            As[kq*4+0][r] = v.x; As[kq*4+1][r] = v.y;
            As[kq*4+2][r] = v.z; As[kq*4+3][r] = v.w;
        }
        #pragma unroll
        for (int i = 0; i < B_LOADS; i++) {
            const int idx = tid + i * THREADS;
            const int r = idx / KQ, kq = idx % KQ;
            const float4 v = *reinterpret_cast<const float4*>(
                &B[(size_t)(colBase + r) * ldb + k0 + kq * 4]);
            Bs[kq*4+0][r] = v.x; Bs[kq*4+1][r] = v.y;
            Bs[kq*4+2][r] = v.z; Bs[kq*4+3][r] = v.w;
        }
        __syncthreads();

        #pragma unroll
        for (int kk = 0; kk < BK; kk++) {
            float ra[TM], rb[TN];
            #pragma unroll
            for (int i = 0; i < TM; i++) ra[i] = As[kk][ty*TM + i];
            #pragma unroll
            for (int j = 0; j < TN; j++) rb[j] = Bs[kk][tx*TN + j];
            #pragma unroll
            for (int i = 0; i < TM; i++)
                #pragma unroll
                for (int j = 0; j < TN; j++)
                    acc[i][j] = fmaf(ra[i], rb[j], acc[i][j]);
        }
        __syncthreads();
    }

    #pragma unroll
    for (int i = 0; i < TM; i++) {
        const int r = rowBase + ty*TM + i;
        #pragma unroll
        for (int j = 0; j < TN; j++) {
            const int c = colBase + tx*TN + j;
            float v = acc[i][j];
            if (EPI == 2) v = softplus_f(v + aux[c]);
            C[(size_t)r * ldc + c] = v;
        }
    }
}

// ---------------------------------------------------------------------------
// Depthwise causal conv + bias + SiLU; 4 timesteps x 4 channels per thread.
// ---------------------------------------------------------------------------
__global__ void conv_silu_kernel(const float* __restrict__ xz,
                                 const float* __restrict__ conv_w,
                                 const float* __restrict__ conv_b,
                                 float* __restrict__ xc,
                                 bf16* __restrict__ xc_hi,
                                 bf16* __restrict__ xc_lo)
{
    const int t  = blockIdx.x * blockDim.x + threadIdx.x;
    const int dq = t & (D_INNER/4 - 1);
    const int rg = t / (D_INNER/4);
    const int l0 = (rg & (SEQ/4 - 1)) * 4;
    const int b  = rg / (SEQ/4);
    const int d0 = dq * 4;

    float4 cw[4];
    #pragma unroll
    for (int i = 0; i < 4; i++)
        cw[i] = *reinterpret_cast<const float4*>(&conv_w[(d0 + i) * D_CONV]);
    const float4 bias = *reinterpret_cast<const float4*>(&conv_b[d0]);

    float4 xv[7];
    #pragma unroll
    for (int k = 0; k < 7; k++) {
        const int ls = l0 - 3 + k;
        if (ls >= 0)
            xv[k] = *reinterpret_cast<const float4*>(
                &xz[((size_t)(b * SEQ + ls)) * (2 * D_INNER) + d0]);
        else
            xv[k] = make_float4(0.f, 0.f, 0.f, 0.f);
    }

    #pragma unroll
    for (int u = 0; u < 4; u++) {
        float4 a;
        a.x = fmaf(xv[u].x,   cw[0].x, fmaf(xv[u+1].x, cw[0].y,
              fmaf(xv[u+2].x, cw[0].z, fmaf(xv[u+3].x, cw[0].w, bias.x))));
        a.y = fmaf(xv[u].y,   cw[1].x, fmaf(xv[u+1].y, cw[1].y,
              fmaf(xv[u+2].y, cw[1].z, fmaf(xv[u+3].y, cw[1].w, bias.y))));
        a.z = fmaf(xv[u].z,   cw[2].x, fmaf(xv[u+1].z, cw[2].y,
              fmaf(xv[u+2].z, cw[2].z, fmaf(xv[u+3].z, cw[2].w, bias.z))));
        a.w = fmaf(xv[u].w,   cw[3].x, fmaf(xv[u+1].w, cw[3].y,
              fmaf(xv[u+2].w, cw[3].z, fmaf(xv[u+3].w, cw[3].w, bias.w))));

        float4 o;
        o.x = a.x / (1.0f + __expf(-a.x));
        o.y = a.y / (1.0f + __expf(-a.y));
        o.z = a.z / (1.0f + __expf(-a.z));
        o.w = a.w / (1.0f + __expf(-a.w));

        const size_t off = ((size_t)(b * SEQ + l0 + u)) * D_INNER + d0;
        *reinterpret_cast<float4*>(&xc[off]) = o;

        bf16 h0,h1,h2,h3,l0b,l1b,l2b,l3b;
        split2(o.x, h0, l0b); split2(o.y, h1, l1b);
        split2(o.z, h2, l2b); split2(o.w, h3, l3b);
        reinterpret_cast<__nv_bfloat162*>(&xc_hi[off])[0] = __halves2bfloat162(h0, h1);
        reinterpret_cast<__nv_bfloat162*>(&xc_hi[off])[1] = __halves2bfloat162(h2, h3);
        reinterpret_cast<__nv_bfloat162*>(&xc_lo[off])[0] = __halves2bfloat162(l0b, l1b);
        reinterpret_cast<__nv_bfloat162*>(&xc_lo[off])[1] = __halves2bfloat162(l2b, l3b);
    }
}

// ---------------------------------------------------------------------------
// Chunked parallel scan (R5 structure, proven).
// ---------------------------------------------------------------------------
__global__ void __launch_bounds__(256)
scanA_kernel(const float* __restrict__ dt,
             const float* __restrict__ proj,
             const float* __restrict__ xc,
             const float* __restrict__ A_log,
             float* __restrict__ P,
             float* __restrict__ q)
{
    const int ch = blockIdx.x & (CH - 1);
    const int bg = blockIdx.x / CH;
    const int b  = bg >> 6, g = bg & 63;
    const int d0 = g * 16;
    const int tid = threadIdx.x;
    const int c = tid >> 4, n = tid & 15;
    const int d = d0 + c;

    __shared__ float sdt[64][16], sxc[64][16], sB[64][16];

    const float Av = -__expf(A_log[d * D_STATE + n]);
    const size_t rowb = (size_t)b * SEQ + ch * CLEN;
    const int lt = tid >> 2, lq = tid & 3;

    float s = 0.0f, dtsum = 0.0f;

    for (int t0 = 0; t0 < CLEN; t0 += 64) {
        __syncthreads();
        {
            const size_t row = rowb + t0 + lt;
            *reinterpret_cast<float4*>(&sdt[lt][lq*4]) =
                *reinterpret_cast<const float4*>(&dt[row * D_INNER + d0 + lq*4]);
            *reinterpret_cast<float4*>(&sxc[lt][lq*4]) =
                *reinterpret_cast<const float4*>(&xc[row * D_INNER + d0 + lq*4]);
            *reinterpret_cast<float4*>(&sB[lt][lq*4]) =
                *reinterpret_cast<const float4*>(&proj[row * 64 + DT_RANK + lq*4]);
        }
        __syncthreads();

        #pragma unroll 8
        for (int t = 0; t < 64; t++) {
            const float dtv = sdt[t][c];
            const float dA  = __expf(dtv * Av);
            s = fmaf(s, dA, dtv * sB[t][n] * sxc[t][c]);
            dtsum += dtv;
        }
    }
    P[(size_t)blockIdx.x * 256 + tid] = __expf(Av * dtsum);
    q[(size_t)blockIdx.x * 256 + tid] = s;
}

__global__ void __launch_bounds__(256)
scanB_kernel(const float* __restrict__ P,
             const float* __restrict__ q,
             float* __restrict__ sin)
{
    const int tid = threadIdx.x;
    float s = 0.0f;
    #pragma unroll
    for (int ch = 0; ch < CH; ch++) {
        const size_t idx = ((size_t)blockIdx.x * CH + ch) * 256 + tid;
        sin[idx] = s;
        s = fmaf(P[idx], s, q[idx]);
    }
}

__global__ void __launch_bounds__(256)
scanC_kernel(const float* __restrict__ dt,
             const float* __restrict__ proj,
             const float* __restrict__ xc,
             const float* __restrict__ xz,
             const float* __restrict__ A_log,
             const float* __restrict__ Dp,
             const float* __restrict__ sin,
             bf16* __restrict__ y_hi,
             bf16* __restrict__ y_lo)
{
    const int ch = blockIdx.x & (CH - 1);
    const int bg = blockIdx.x / CH;
    const int b  = bg >> 6, g = bg & 63;
    const int d0 = g * 16;
    const int tid = threadIdx.x;
    const int c = tid >> 4, n = tid & 15;
    const int d = d0 + c;

    __shared__ float sdt[64][16], sxc[64][16], sz[64][16];
    __shared__ float sBC[64][32];
    __shared__ float sy [64][16];

    const float Av = -__expf(A_log[d * D_STATE + n]);
    const float Dv = Dp[d];
    const size_t rowb = (size_t)b * SEQ + ch * CLEN;
    const int lt = tid >> 2, lq = tid & 3;

    float s = sin[(size_t)blockIdx.x * 256 + tid];

    for (int t0 = 0; t0 < CLEN; t0 += 64) {
        __syncthreads();
        {
            const size_t row = rowb + t0 + lt;
            *reinterpret_cast<float4*>(&sdt[lt][lq*4]) =
                *reinterpret_cast<const float4*>(&dt[row * D_INNER + d0 + lq*4]);
            *reinterpret_cast<float4*>(&sxc[lt][lq*4]) =
                *reinterpret_cast<const float4*>(&xc[row * D_INNER + d0 + lq*4]);
            *reinterpret_cast<float4*>(&sz[lt][lq*4]) =
                *reinterpret_cast<const float4*>(
                    &xz[row * 2 * D_INNER + D_INNER + d0 + lq*4]);
            *reinterpret_cast<float4*>(&sBC[lt][lq*4]) =
                *reinterpret_cast<const float4*>(&proj[row * 64 + DT_RANK + lq*4]);
            *reinterpret_cast<float4*>(&sBC[lt][16 + lq*4]) =
                *reinterpret_cast<const float4*>(
                    &proj[row * 64 + DT_RANK + D_STATE + lq*4]);
        }
        __syncthreads();

        #pragma unroll 8
        for (int t = 0; t < 64; t++) {
            const float dtv = sdt[t][c];
            const float xcv = sxc[t][c];
            const float dA  = __expf(dtv * Av);
            s = fmaf(s, dA, dtv * sBC[t][n] * xcv);
            float part = s * sBC[t][16 + n];
            part += __shfl_xor_sync(0xffffffffu, part, 8);
            part += __shfl_xor_sync(0xffffffffu, part, 4);
            part += __shfl_xor_sync(0xffffffffu, part, 2);
            part += __shfl_xor_sync(0xffffffffu, part, 1);
            if (n == 0) {
                const float zz = sz[t][c];
                sy[t][c] = (part + xcv * Dv) * (zz / (1.0f + __expf(-zz)));
            }
        }
        __syncthreads();
        {
            const float4 v = *reinterpret_cast<const float4*>(&sy[lt][lq*4]);
            const size_t o = (rowb + t0 + lt) * D_INNER + d0 + lq*4;
            bf16 h0,h1,h2,h3,l0,l1,l2,l3;
            split2(v.x, h0, l0); split2(v.y, h1, l1);
            split2(v.z, h2, l2); split2(v.w, h3, l3);
            reinterpret_cast<__nv_bfloat162*>(&y_hi[o])[0] = __halves2bfloat162(h0, h1);
            reinterpret_cast<__nv_bfloat162*>(&y_hi[o])[1] = __halves2bfloat162(h2, h3);
            reinterpret_cast<__nv_bfloat162*>(&y_lo[o])[0] = __halves2bfloat162(l0, l1);
            reinterpret_cast<__nv_bfloat162*>(&y_lo[o])[1] = __halves2bfloat162(l2, l3);
        }
    }
}

// ---------------------------------------------------------------------------
// Launch sequence
// ---------------------------------------------------------------------------
extern "C" void kernel_launch(void* const* d_in, const int* in_sizes, int n_in,
                              void* d_out, int out_size)
{
    const float* x      = (const float*)d_in[0];
    const float* ln_g   = (const float*)d_in[1];
    const float* ln_b   = (const float*)d_in[2];
    const float* W_in   = (const float*)d_in[3];
    const float* conv_w = (const float*)d_in[4];
    const float* conv_b = (const float*)d_in[5];
    const float* W_xprj = (const float*)d_in[6];
    const float* W_dt   = (const float*)d_in[7];
    const float* b_dt   = (const float*)d_in[8];
    const float* A_log  = (const float*)d_in[9];
    const float* Dp     = (const float*)d_in[10];
    const float* W_out  = (const float*)d_in[11];
    float* out = (float*)d_out;

    float *p_xz, *p_xc, *p_proj, *p_dt, *p_P, *p_q, *p_sin;
    bf16 *p_hh, *p_hl, *p_xch, *p_xcl, *p_yh, *p_yl;
    bf16 *p_wih, *p_wil, *p_wxh, *p_wxl, *p_woh, *p_wol;
    cudaGetSymbolAddress((void**)&p_xz,   g_xz);
    cudaGetSymbolAddress((void**)&p_xc,   g_xc);
    cudaGetSymbolAddress((void**)&p_proj, g_proj);
    cudaGetSymbolAddress((void**)&p_dt,   g_dt);
    cudaGetSymbolAddress((void**)&p_P,    g_P);
    cudaGetSymbolAddress((void**)&p_q,    g_q);
    cudaGetSymbolAddress((void**)&p_sin,  g_sin);
    cudaGetSymbolAddress((void**)&p_hh,   g_h_hi);
    cudaGetSymbolAddress((void**)&p_hl,   g_h_lo);
    cudaGetSymbolAddress((void**)&p_xch,  g_xc_hi);
    cudaGetSymbolAddress((void**)&p_xcl,  g_xc_lo);
    cudaGetSymbolAddress((void**)&p_yh,   g_y_hi);
    cudaGetSymbolAddress((void**)&p_yl,   g_y_lo);
    cudaGetSymbolAddress((void**)&p_wih,  g_Win_hi);
    cudaGetSymbolAddress((void**)&p_wil,  g_Win_lo);
    cudaGetSymbolAddress((void**)&p_wxh,  g_Wxp_hi);
    cudaGetSymbolAddress((void**)&p_wxl,  g_Wxp_lo);
    cudaGetSymbolAddress((void**)&p_woh,  g_Wout_hi);
    cudaGetSymbolAddress((void**)&p_wol,  g_Wout_lo);

    // dyn smem: 2 stages * 2 parts * (SA + SB) bf16 * 2 bytes
    const int smemG = 2 * 2 * (128*40 + 64*40) * 2;    // 61440 (128x64)
    const int smemP = 2 * 2 * ( 32*40 + 64*40) * 2;    // 30720
    cudaFuncSetAttribute((const void*)mma_gemm<128,64,32,2,4,0,3>,
                         cudaFuncAttributeMaxDynamicSharedMemorySize, smemG);
    cudaFuncSetAttribute((const void*)mma_gemm<128,64,32,2,4,1,3>,
                         cudaFuncAttributeMaxDynamicSharedMemorySize, smemG);
    cudaFuncSetAttribute((const void*)mma_gemm<32,64,32,2,4,0,3>,
                         cudaFuncAttributeMaxDynamicSharedMemorySize, smemP);

    // 0+1. merged prep: LayerNorm (+split) AND all weight splits, one launch
    prep_kernel<<<LN_BLOCKS + SPLIT_BLOCKS, 256>>>(
        x, ln_g, ln_b, W_in, W_xprj, W_out,
        p_hh, p_hl, p_wih, p_wil, p_wxh, p_wxl, p_woh, p_wol);

    // 2. xz = h @ W_in^T    (4096 x 2048 x 512)  tensor cores, 3 CTA/SM
    mma_gemm<128,64,32,2,4,0,3><<<dim3(2*D_INNER/64, MROWS/128), 256, smemG>>>(
        p_hh, p_hl, DIM, p_wih, p_wil, DIM, p_xz, 2*D_INNER, DIM, nullptr, 0);

    // 3. conv + silu (+ split), 4x4 blocked
    conv_silu_kernel<<<(MROWS/4) * (D_INNER/4) / 256, 256>>>(
        p_xz, conv_w, conv_b, p_xc, p_xch, p_xcl);

    // 4. proj = xc @ W_xproj^T (4096 x 64 x 1024)  tensor cores
    mma_gemm<32,64,32,2,4,0,3><<<dim3(1, MROWS/32), 256, smemP>>>(
        p_xch, p_xcl, D_INNER, p_wxh, p_wxl, D_INNER, p_proj, 64, D_INNER,
        nullptr, 0);

    // 5. dt = softplus(proj[:, :32] @ W_dt^T + b_dt)  (4096 x 1024 x 32) SIMT
    gemm_nt<64,64,16,4,4,2><<<dim3(D_INNER/64, MROWS/64), 256>>>(
        p_proj, 64, W_dt, DT_RANK, p_dt, D_INNER, DT_RANK, b_dt, 0);

    // 6. SSM scan (chunk-parallel, 3 phases) + gating (+ split of y)
    scanA_kernel<<<BATCH * 64 * CH, 256>>>(p_dt, p_proj, p_xc, A_log, p_P, p_q);
    scanB_kernel<<<BATCH * 64, 256>>>(p_P, p_q, p_sin);
    scanC_kernel<<<BATCH * 64 * CH, 256>>>(
        p_dt, p_proj, p_xc, p_xz, A_log, Dp, p_sin, p_yh, p_yl);

    // 7. out = y @ W_out^T + x (4096 x 512 x 1024)  tensor cores, 3 CTA/SM
    mma_gemm<128,64,32,2,4,1,3><<<dim3(DIM/64, MROWS/128), 256, smemG>>>(
        p_yh, p_yl, D_INNER, p_woh, p_wol, D_INNER, out, DIM, D_INNER, x, DIM);
}